// round 1
// baseline (speedup 1.0000x reference)
#include <cuda_runtime.h>
#include <cuda_bf16.h>
#include <cstdint>

// VDP dropout: keep = (u >= 0.1)
//   mu_out    = mu_in    * keep / 0.9
//   Sigma_out = Sigma_in * keep / 768
// Pure streaming elementwise kernel; HBM-bound. float4 vectorized.

static constexpr float DROP_PROP = 0.1f;
static constexpr float INV_KEEP  = 1.0f / (1.0f - DROP_PROP);   // 1/0.9
static constexpr float INV_D     = 1.0f / 768.0f;

__global__ void __launch_bounds__(256)
vdp_dropout_kernel(const float4* __restrict__ mu,
                   const float4* __restrict__ sigma,
                   const float4* __restrict__ u,
                   float4* __restrict__ mu_out,
                   float4* __restrict__ sigma_out,
                   int n4)
{
    int i = blockIdx.x * blockDim.x + threadIdx.x;
    if (i >= n4) return;

    float4 m = mu[i];
    float4 s = sigma[i];
    float4 r = u[i];

    // keep * scale in one value: k = (r >= 0.1) ? scale : 0
    float4 mo, so;
    {
        float km0 = (r.x >= DROP_PROP) ? INV_KEEP : 0.0f;
        float km1 = (r.y >= DROP_PROP) ? INV_KEEP : 0.0f;
        float km2 = (r.z >= DROP_PROP) ? INV_KEEP : 0.0f;
        float km3 = (r.w >= DROP_PROP) ? INV_KEEP : 0.0f;
        mo.x = m.x * km0; mo.y = m.y * km1; mo.z = m.z * km2; mo.w = m.w * km3;

        float ks0 = (r.x >= DROP_PROP) ? INV_D : 0.0f;
        float ks1 = (r.y >= DROP_PROP) ? INV_D : 0.0f;
        float ks2 = (r.z >= DROP_PROP) ? INV_D : 0.0f;
        float ks3 = (r.w >= DROP_PROP) ? INV_D : 0.0f;
        so.x = s.x * ks0; so.y = s.y * ks1; so.z = s.z * ks2; so.w = s.w * ks3;
    }

    mu_out[i]    = mo;
    sigma_out[i] = so;
}

extern "C" void kernel_launch(void* const* d_in, const int* in_sizes, int n_in,
                              void* d_out, int out_size)
{
    const float* mu    = (const float*)d_in[0];
    const float* sigma = (const float*)d_in[1];
    const float* u     = (const float*)d_in[2];
    float* out = (float*)d_out;

    int n = in_sizes[0];            // 9,683,456 elements
    int n4 = n / 4;                 // divisible by 4 (D=768)

    float* mu_out    = out;         // outputs concatenated: (mu_out, Sigma_out)
    float* sigma_out = out + n;

    int threads = 256;
    int blocks = (n4 + threads - 1) / threads;
    vdp_dropout_kernel<<<blocks, threads>>>(
        (const float4*)mu, (const float4*)sigma, (const float4*)u,
        (float4*)mu_out, (float4*)sigma_out, n4);
}